// round 16
// baseline (speedup 1.0000x reference)
#include <cuda_runtime.h>

#define N_TOK 1024
#define HD    256
#define ED    128
#define TN    12
#define ON    3
#define NHOPS 4
#define NB    36
#define W1STR (384*256)
#define W2STR (256*256)
#define MTILE 8           // tokens per fused tile (both layers in-CTA)
#define MAXT  164         // max tiles/hop: 1024/8 + 36 partials
#define XS_STR 260
#define KBF   16          // K-rows per W smem chunk
#define NCHF  (HD/KBF)    // 16 chunks
#define WCH   (KBF*HD)    // floats per chunk (4096)

// dynamic smem layout (floats):
//   ws[3][WCH] | xs[8*XS_STR] | hs[8*XS_STR] | cs[256] | tok_s[8]
#define SMEM_FLOATS (3*WCH + 2*(MTILE*XS_STR) + HD + 8)

// ---- scratch (no device allocation allowed) ----
__device__ float g_state[N_TOK * HD];
__device__ float g_b1eff[NB * HD];
__device__ int   g_perm[NHOPS][N_TOK];
__device__ int   g_tinfo[NHOPS][MAXT];   // bkt | poff<<6 | mcnt<<17
__device__ int   g_ntiles[NHOPS];

// ============================================================
// 0) fused prep: blocks 0..255 copy x->g_state (reshape identity),
//    blocks 256..291 fold op-emb half of W1 + b1 -> g_b1eff,
//    block 292 buckets all 4 hops (atomics; output order-invariant).
// ============================================================
__global__ void __launch_bounds__(256)
prep_kernel(const float* __restrict__ x,
            const float* __restrict__ W1, const float* __restrict__ b1,
            const float* __restrict__ emb,
            const int* __restrict__ st, const int* __restrict__ so) {
    int blk = blockIdx.x, tid = threadIdx.x;
    if (blk < 256) {
        int i = blk * 256 + tid;
        ((float4*)g_state)[i] = ((const float4*)x)[i];
    } else if (blk < 256 + NB) {
        int bkt = blk - 256, o = tid;
        const float* wE = W1 + (size_t)bkt * W1STR + 256 * HD + o;
        const float* ev = emb + bkt * ED;
        float acc = b1[bkt * HD + o];
#pragma unroll 8
        for (int e = 0; e < ED; e++) acc += ev[e] * wE[e * HD];
        g_b1eff[bkt * HD + o] = acc;
    } else {
        __shared__ int cnt[NB];
        __shared__ int base[NB];
        bool act[4] = {true, true, true, true};
        for (int hop = 0; hop < NHOPS; hop++) {
            if (tid < NB) cnt[tid] = 0;
            __syncthreads();
            int bb[4], rr[4];
#pragma unroll
            for (int j = 0; j < 4; j++) {
                int n = tid + 256 * j;
                act[j] = act[j] && (st[hop * N_TOK + n] != TN);
                if (act[j]) {
                    bb[j] = st[hop * N_TOK + n] * ON + so[hop * N_TOK + n];
                    rr[j] = atomicAdd(&cnt[bb[j]], 1);
                }
            }
            __syncthreads();
            if (tid == 0) {
                int s = 0, nt = 0;
                for (int i = 0; i < NB; i++) {
                    base[i] = s;
                    int c = cnt[i];
                    for (int off = 0; off < c; off += MTILE) {
                        int mc = c - off; if (mc > MTILE) mc = MTILE;
                        g_tinfo[hop][nt++] = i | ((s + off) << 6) | (mc << 17);
                    }
                    s += c;
                }
                g_ntiles[hop] = nt;
            }
            __syncthreads();
#pragma unroll
            for (int j = 0; j < 4; j++)
                if (act[j]) g_perm[hop][base[bb[j]] + rr[j]] = tid + 256 * j;
            __syncthreads();
        }
    }
}

// ============================================================
// 1) fused hop kernel: one CTA owns 8 tokens through BOTH layers.
//    Thread map: og2 = tid&127 (output float2), toks {tg, tg+2,
//    tg+4, tg+6} with tg = tid>>7  ->  w LDS is float2 with only
//    2-way warp redundancy (16 crossbar cyc/k, under the 32 cyc/k
//    FFMA floor).  W staged in triple-buffered 16x256 chunks
//    (prefetch distance 2), h kept in smem between layers.
// ============================================================
__global__ void __launch_bounds__(256, 1)
hop_kernel(int hop, const float* __restrict__ W1,
           const float* __restrict__ W2, const float* __restrict__ b2) {
    extern __shared__ float smem[];
    float* ws    = smem;                       // 3 * 4096
    float* xs    = ws + 3 * WCH;               // 8 * XS_STR
    float* hs    = xs + MTILE * XS_STR;        // 8 * XS_STR
    float* cs    = hs + MTILE * XS_STR;        // 256
    int*   tok_s = (int*)(cs + HD);            // 8

    int nt  = g_ntiles[hop];
    int tid = threadIdx.x;
    int og2 = tid & 127;          // output pair: outs {og2*2, og2*2+1}
    int tg  = tid >> 7;           // token base: toks {tg, tg+2, tg+4, tg+6}

    // staging coords: row kl in chunk, 16 consecutive floats per thread
    int kl  = tid >> 4;
    int cf  = (tid & 15) << 4;

    for (int tix = blockIdx.x; tix < nt; tix += gridDim.x) {
        __syncthreads();                       // prev tile fully done
        int info = g_tinfo[hop][tix];
        int bkt  = info & 63;
        int poff = (info >> 6) & 2047;
        int mcnt = info >> 17;

        if (tid < MTILE) tok_s[tid] = (tid < mcnt) ? g_perm[hop][poff + tid] : -1;
        __syncthreads();

        // gather x tile: 8 tok x 64 float4, 2 per thread (zero-pad dead rows)
        {
            int r = tid >> 5, c4 = tid & 31;
            const float* src = (tok_s[r] >= 0) ? g_state + tok_s[r] * HD : 0;
            float4 v0 = src ? *(const float4*)(src + c4 * 4)
                            : make_float4(0.f, 0.f, 0.f, 0.f);
            float4 v1 = src ? *(const float4*)(src + (c4 + 32) * 4)
                            : make_float4(0.f, 0.f, 0.f, 0.f);
            *(float4*)(xs + r * XS_STR + c4 * 4)        = v0;
            *(float4*)(xs + r * XS_STR + (c4 + 32) * 4) = v1;
        }

#pragma unroll
        for (int layer = 0; layer < 2; layer++) {
            const float* Wb   = layer ? W2 + (size_t)bkt * W2STR
                                      : W1 + (size_t)bkt * W1STR;
            const float* bias = layer ? b2 + bkt * HD : g_b1eff + bkt * HD;
            const float* xin  = layer ? hs : xs;

            __syncthreads();      // xs/hs ready; prev layer done with ws/cs
            cs[tid] = bias[tid];

            // prologue: stage chunks 0 and 1
            const float* wthr = Wb + kl * HD + cf;     // this thread's slice
#pragma unroll
            for (int pc = 0; pc < 2; pc++) {
                const float* src = wthr + pc * KBF * HD;
                float* dst = ws + pc * WCH + kl * HD + cf;
                *(float4*)(dst)      = *(const float4*)(src);
                *(float4*)(dst + 4)  = *(const float4*)(src + 4);
                *(float4*)(dst + 8)  = *(const float4*)(src + 8);
                *(float4*)(dst + 12) = *(const float4*)(src + 12);
            }
            __syncthreads();

            float a00 = 0.f, a01 = 0.f, a10 = 0.f, a11 = 0.f;
            float a20 = 0.f, a21 = 0.f, a30 = 0.f, a31 = 0.f;
            const float* xr0 = xin + tg * XS_STR;
            const float* xr1 = xin + (tg + 2) * XS_STR;
            const float* xr2 = xin + (tg + 4) * XS_STR;
            const float* xr3 = xin + (tg + 6) * XS_STR;

            for (int c = 0; c < NCHF; c++) {
                float4 q0, q1, q2, q3;
                bool pf = (c + 2 < NCHF);
                if (pf) {
                    const float* src = wthr + (c + 2) * KBF * HD;
                    q0 = *(const float4*)(src);
                    q1 = *(const float4*)(src + 4);
                    q2 = *(const float4*)(src + 8);
                    q3 = *(const float4*)(src + 12);
                }
                const float* wb = ws + (c % 3) * WCH + og2 * 2;
#pragma unroll
                for (int k4 = 0; k4 < KBF / 4; k4++) {
                    float4 xv0 = *(const float4*)(xr0 + c * KBF + k4 * 4);
                    float4 xv1 = *(const float4*)(xr1 + c * KBF + k4 * 4);
                    float4 xv2 = *(const float4*)(xr2 + c * KBF + k4 * 4);
                    float4 xv3 = *(const float4*)(xr3 + c * KBF + k4 * 4);
#pragma unroll
                    for (int j = 0; j < 4; j++) {
                        float2 w = *(const float2*)(wb + (k4 * 4 + j) * HD);
                        float x0 = (j == 0) ? xv0.x : (j == 1) ? xv0.y : (j == 2) ? xv0.z : xv0.w;
                        float x1 = (j == 0) ? xv1.x : (j == 1) ? xv1.y : (j == 2) ? xv1.z : xv1.w;
                        float x2 = (j == 0) ? xv2.x : (j == 1) ? xv2.y : (j == 2) ? xv2.z : xv2.w;
                        float x3 = (j == 0) ? xv3.x : (j == 1) ? xv3.y : (j == 2) ? xv3.z : xv3.w;
                        a00 += x0 * w.x; a01 += x0 * w.y;
                        a10 += x1 * w.x; a11 += x1 * w.y;
                        a20 += x2 * w.x; a21 += x2 * w.y;
                        a30 += x3 * w.x; a31 += x3 * w.y;
                    }
                }
                if (pf) {
                    float* dst = ws + ((c + 2) % 3) * WCH + kl * HD + cf;
                    *(float4*)(dst)      = q0;
                    *(float4*)(dst + 4)  = q1;
                    *(float4*)(dst + 8)  = q2;
                    *(float4*)(dst + 12) = q3;
                }
                __syncthreads();
            }

            float2 cv = *(const float2*)(cs + og2 * 2);
            float2 r0, r1, r2, r3;
            r0.x = fmaxf(a00 + cv.x, 0.f); r0.y = fmaxf(a01 + cv.y, 0.f);
            r1.x = fmaxf(a10 + cv.x, 0.f); r1.y = fmaxf(a11 + cv.y, 0.f);
            r2.x = fmaxf(a20 + cv.x, 0.f); r2.y = fmaxf(a21 + cv.y, 0.f);
            r3.x = fmaxf(a30 + cv.x, 0.f); r3.y = fmaxf(a31 + cv.y, 0.f);

            if (layer == 0) {     // h -> smem (padded rows too; harmless)
                *(float2*)(hs + tg * XS_STR + og2 * 2)       = r0;
                *(float2*)(hs + (tg + 2) * XS_STR + og2 * 2) = r1;
                *(float2*)(hs + (tg + 4) * XS_STR + og2 * 2) = r2;
                *(float2*)(hs + (tg + 6) * XS_STR + og2 * 2) = r3;
            } else {              // y -> state (active rows only)
                if (tg < mcnt)
                    *(float2*)(g_state + tok_s[tg] * HD + og2 * 2) = r0;
                if (tg + 2 < mcnt)
                    *(float2*)(g_state + tok_s[tg + 2] * HD + og2 * 2) = r1;
                if (tg + 4 < mcnt)
                    *(float2*)(g_state + tok_s[tg + 4] * HD + og2 * 2) = r2;
                if (tg + 6 < mcnt)
                    *(float2*)(g_state + tok_s[tg + 6] * HD + og2 * 2) = r3;
            }
        }
    }
}

// ============================================================
// 2) pool(8) + LayerNorm + 256x10 head.  Deterministic shuffle trees.
// ============================================================
__global__ void __launch_bounds__(256)
head_kernel(const float* __restrict__ ln_g, const float* __restrict__ ln_b,
            const float* __restrict__ Wt,   const float* __restrict__ bt,
            float* __restrict__ out) {
    int b = blockIdx.x, col = threadIdx.x;
    float s = 0.f;
#pragma unroll
    for (int p = 0; p < 8; p++) s += g_state[(b * 8 + p) * HD + col];
    float pooled = s * 0.125f;

    float v = pooled, v2 = pooled * pooled;
#pragma unroll
    for (int off = 16; off; off >>= 1) {
        v  += __shfl_down_sync(0xffffffffu, v,  off);
        v2 += __shfl_down_sync(0xffffffffu, v2, off);
    }
    __shared__ float wsum[8], wsum2[8];
    __shared__ float mu_s, rstd_s;
    int w = col >> 5, l = col & 31;
    if (l == 0) { wsum[w] = v; wsum2[w] = v2; }
    __syncthreads();
    if (col == 0) {
        float S = 0.f, S2 = 0.f;
#pragma unroll
        for (int i = 0; i < 8; i++) { S += wsum[i]; S2 += wsum2[i]; }
        float mu  = S * (1.f / 256.f);
        float var = S2 * (1.f / 256.f) - mu * mu;
        mu_s = mu; rstd_s = rsqrtf(var + 1e-5f);
    }
    __syncthreads();
    float normed = (pooled - mu_s) * rstd_s * ln_g[col] + ln_b[col];

    float p[10];
#pragma unroll
    for (int c = 0; c < 10; c++) p[c] = normed * Wt[col * 10 + c];
#pragma unroll
    for (int off = 16; off; off >>= 1)
#pragma unroll
        for (int c = 0; c < 10; c++) p[c] += __shfl_down_sync(0xffffffffu, p[c], off);

    __shared__ float pr[8][10];
    if (l == 0)
#pragma unroll
        for (int c = 0; c < 10; c++) pr[w][c] = p[c];
    __syncthreads();
    if (col < 10) {
        float acc = bt[col];
#pragma unroll
        for (int i = 0; i < 8; i++) acc += pr[i][col];
        out[b * 10 + col] = acc;
    }
}

// ============================================================
extern "C" void kernel_launch(void* const* d_in, const int* in_sizes, int n_in,
                              void* d_out, int out_size) {
    const float* x    = (const float*)d_in[0];
    const float* W1   = (const float*)d_in[1];
    const float* b1   = (const float*)d_in[2];
    const float* W2   = (const float*)d_in[3];
    const float* b2   = (const float*)d_in[4];
    const float* emb  = (const float*)d_in[5];
    const float* ln_g = (const float*)d_in[6];
    const float* ln_b = (const float*)d_in[7];
    const float* Wt   = (const float*)d_in[8];
    const float* bt   = (const float*)d_in[9];
    const int*   st   = (const int*)d_in[10];
    const int*   so   = (const int*)d_in[11];
    float* out = (float*)d_out;
    (void)in_sizes; (void)n_in; (void)out_size;

    const int shmem = SMEM_FLOATS * (int)sizeof(float);
    cudaFuncSetAttribute(hop_kernel,
                         cudaFuncAttributeMaxDynamicSharedMemorySize, shmem);

    prep_kernel<<<256 + NB + 1, 256>>>(x, W1, b1, emb, st, so);
    for (int hop = 0; hop < NHOPS; hop++)
        hop_kernel<<<MAXT, 256, shmem>>>(hop, W1, W2, b2);
    head_kernel<<<128, 256>>>(ln_g, ln_b, Wt, bt, out);
}